// round 16
// baseline (speedup 1.0000x reference)
#include <cuda_runtime.h>
#include <cuda_fp16.h>
#include <math.h>
#include <stdint.h>

#define B_ 2
#define L_ 1024
#define D_ 768
#define H_ 12
#define HD_ 64
#define FF_ 3072
#define V_ 32000
#define NL_ 2
#define TOK_BOS 1
#define TOK_SEP 2
#define WIN_ 512
#define EPS_ 1e-5f
#define M_ (B_ * L_) /* 2048 rows */

// ---------------- scratch (static device globals; no allocation) ------------
__device__ float g_x[M_ * D_];
__device__ float g_qkv[M_ * 3 * D_];
__device__ int   g_seg[B_ * L_];
__device__ int   g_gkey[B_ * L_];
__device__ int   g_valid[B_ * L_];

// fragment-major fp16x2 operand buffers (uint32 = 2 packed halves)
__device__ unsigned g_ht[M_ * D_ / 2];
__device__ unsigned g_yt[M_ * D_ / 2];
__device__ unsigned g_ft[M_ * FF_ / 2];
__device__ unsigned g_wqt[NL_ * 3 * D_ * D_ / 2];
__device__ unsigned g_wot[NL_ * D_ * D_ / 2];
__device__ unsigned g_w1t[NL_ * FF_ * D_ / 2];
__device__ unsigned g_w2t[NL_ * D_ * FF_ / 2];
__device__ unsigned g_wht[V_ * D_ / 2];

// ---------------- helpers ----------------------------------------------------
__device__ __forceinline__ unsigned f2h2(float a, float b) {
    __half2 h = __floats2half2_rn(a, b);
    return *(unsigned*)&h;
}
__device__ __forceinline__ uint32_t smem_u32(const void* p) {
    uint32_t a;
    asm("{ .reg .u64 t; cvta.to.shared.u64 t, %1; cvt.u32.u64 %0, t; }" : "=r"(a) : "l"(p));
    return a;
}
__device__ __forceinline__ void cpa16(uint32_t s, const void* g) {
    asm volatile("cp.async.cg.shared.global [%0], [%1], 16;" :: "r"(s), "l"(g));
}
#define CP_COMMIT() asm volatile("cp.async.commit_group;" ::: "memory")
#define CP_WAIT2()  asm volatile("cp.async.wait_group 2;" ::: "memory")
#define CP_WAIT1()  asm volatile("cp.async.wait_group 1;" ::: "memory")
#define CP_WAIT0()  asm volatile("cp.async.wait_group 0;" ::: "memory")

// fp16 m16n8k16
__device__ __forceinline__ void mma16(float* c, const unsigned* a, const unsigned* b) {
    asm volatile(
        "mma.sync.aligned.m16n8k16.row.col.f32.f16.f16.f32 "
        "{%0,%1,%2,%3}, {%4,%5,%6,%7}, {%8,%9}, {%0,%1,%2,%3};\n"
        : "+f"(c[0]), "+f"(c[1]), "+f"(c[2]), "+f"(c[3])
        : "r"(a[0]), "r"(a[1]), "r"(a[2]), "r"(a[3]), "r"(b[0]), "r"(b[1]));
}

// fp16 fragment-major uint indices: 1024 uints per (128row x 16k) slab.
__device__ __forceinline__ size_t a16u(int Kd, int m, int c) {
    return ((size_t)(m >> 7) * (Kd >> 4) + (c >> 4)) * 1024
         + (size_t)(((m & 127) >> 4) * 128)
         + (((m & 7) * 4 + ((c >> 1) & 3)) << 2)
         + ((m & 15) >> 3) + 2 * ((c & 15) >> 3);
}
__device__ __forceinline__ size_t b16u(int Kd, int n, int k) {
    return ((size_t)(n >> 7) * (Kd >> 4) + (k >> 4)) * 1024
         + (size_t)(((n & 127) >> 4) * 128)
         + (((n & 7) * 4 + ((k >> 1) & 3)) << 2)
         + ((k & 15) >> 3) + 2 * ((n & 15) >> 3);
}
// fp16 64x64 attention-tile fragment indices (uint index)
// per-warp Q/P A-frag: 4 k16-slabs x 128 uints
__device__ __forceinline__ int q16u(int w, int m, int k) {
    return (w * 4 + (k >> 4)) * 128
         + (((m & 7) * 4 + ((k >> 1) & 3)) << 2)
         + ((m & 15) >> 3) + 2 * ((k & 15) >> 3);
}
// K/V^T B-frag: 4 k16-slabs x 512 uints (4 n16 pair-groups x 128)
__device__ __forceinline__ int kb16u(int n, int k) {
    return (k >> 4) * 512 + (n >> 4) * 128
         + (((n & 7) * 4 + ((k >> 1) & 3)) << 2)
         + ((k & 15) >> 3) + 2 * ((n & 15) >> 3);
}

// ---------------- embedding -------------------------------------------------
__global__ void k_embed(const int* __restrict__ tokens, const int* __restrict__ types,
                        const float* __restrict__ tok_emb, const float* __restrict__ type_emb,
                        const float* __restrict__ pos_emb) {
    int idx = blockIdx.x * blockDim.x + threadIdx.x;
    if (idx >= M_ * D_) return;
    int d = idx % D_;
    int bl = idx / D_;
    int l = bl % L_;
    g_x[idx] = tok_emb[(size_t)tokens[bl] * D_ + d]
             + type_emb[(size_t)types[bl] * D_ + d]
             + pos_emb[(size_t)l * D_ + d];
}

// ---------------- mask metadata ----------------------------------------------
__global__ void k_maskprep(const int* __restrict__ tokens, const int* __restrict__ attn_mask) {
    int b = threadIdx.x;
    if (b >= B_) return;
    int seg = 0;
    for (int l = 0; l < L_; l++) {
        int i = b * L_ + l;
        int va = attn_mask[i] != 0;
        int tok = tokens[i];
        int is_sep = (tok == TOK_SEP) && va;
        seg += is_sep;
        g_seg[i] = seg;
        g_gkey[i] = (((tok == TOK_BOS) && va) || is_sep) ? 1 : 0;
        g_valid[i] = va;
    }
}

// ---------------- all weight conversions (pair-packed uint stores) ----------
#define SZ_WQ (NL_ * 3 * D_ * D_)
#define SZ_WO (NL_ * D_ * D_)
#define SZ_W1 (NL_ * FF_ * D_)
#define SZ_W2 (NL_ * D_ * FF_)
#define SZ_WH (V_ * D_)
#define CVT_PAIRS ((SZ_WQ + SZ_WO + SZ_W1 + SZ_W2 + SZ_WH) / 2)

__global__ void k_cvt_all(const float* __restrict__ qkv_w, const float* __restrict__ out_w,
                          const float* __restrict__ ff_w1, const float* __restrict__ ff_w2,
                          const float* __restrict__ head_w) {
    long p = (long)blockIdx.x * 256 + threadIdx.x;
    if (p < SZ_WQ / 2) {
        int n = (int)(p / (D_ / 2)), k = 2 * (int)(p % (D_ / 2));
        const float* w = qkv_w + (size_t)n * D_ + k;
        g_wqt[b16u(D_, n, k)] = f2h2(w[0], w[1]);
        return;
    }
    p -= SZ_WQ / 2;
    if (p < SZ_WO / 2) {
        int n = (int)(p / (D_ / 2)), k = 2 * (int)(p % (D_ / 2));
        const float* w = out_w + (size_t)n * D_ + k;
        g_wot[b16u(D_, n, k)] = f2h2(w[0], w[1]);
        return;
    }
    p -= SZ_WO / 2;
    if (p < SZ_W1 / 2) {
        int n = (int)(p / (D_ / 2)), k = 2 * (int)(p % (D_ / 2));
        const float* w = ff_w1 + (size_t)n * D_ + k;
        g_w1t[b16u(D_, n, k)] = f2h2(w[0], w[1]);
        return;
    }
    p -= SZ_W1 / 2;
    if (p < SZ_W2 / 2) {
        int n = (int)(p / (FF_ / 2)), k = 2 * (int)(p % (FF_ / 2));
        const float* w = ff_w2 + (size_t)n * FF_ + k;
        g_w2t[b16u(FF_, n, k)] = f2h2(w[0], w[1]);
        return;
    }
    p -= SZ_W2 / 2;
    if (p < SZ_WH / 2) {
        int n = (int)(p / (D_ / 2)), k = 2 * (int)(p % (D_ / 2));
        const float* w = head_w + (size_t)n * D_ + k;
        g_wht[b16u(D_, n, k)] = f2h2(w[0], w[1]);
    }
}

// ---------------- layernorm -> A-tiled fp16 ----------------------------------
__global__ __launch_bounds__(256)
void k_ln_t(const float* __restrict__ x, const float* __restrict__ sc,
            const float* __restrict__ bi, unsigned* __restrict__ out) {
    int row = blockIdx.x;
    const float* xr = x + (size_t)row * D_;
    int t = threadIdx.x;
    float v0 = xr[t], v1 = xr[t + 256], v2 = xr[t + 512];
    float s = v0 + v1 + v2;
    float ss = v0 * v0 + v1 * v1 + v2 * v2;
    __shared__ float rs[8], rq[8];
#pragma unroll
    for (int o = 16; o > 0; o >>= 1) {
        s  += __shfl_xor_sync(0xffffffffu, s, o);
        ss += __shfl_xor_sync(0xffffffffu, ss, o);
    }
    if ((t & 31) == 0) { rs[t >> 5] = s; rq[t >> 5] = ss; }
    __syncthreads();
    if (t < 32) {
        float a = (t < 8) ? rs[t] : 0.f;
        float q = (t < 8) ? rq[t] : 0.f;
#pragma unroll
        for (int o = 4; o > 0; o >>= 1) {
            a += __shfl_xor_sync(0xffffffffu, a, o);
            q += __shfl_xor_sync(0xffffffffu, q, o);
        }
        if (t == 0) { rs[0] = a; rq[0] = q; }
    }
    __syncthreads();
    float mean = rs[0] * (1.0f / D_);
    float var  = rq[0] * (1.0f / D_) - mean * mean;
    float inv = rsqrtf(var + EPS_);
    __half* oh = (__half*)out;
    oh[2 * a16u(D_, row, t)       + (t & 1)] = __float2half_rn((v0 - mean) * inv * sc[t]       + bi[t]);
    oh[2 * a16u(D_, row, t + 256) + (t & 1)] = __float2half_rn((v1 - mean) * inv * sc[t + 256] + bi[t + 256]);
    oh[2 * a16u(D_, row, t + 512) + (t & 1)] = __float2half_rn((v2 - mean) * inv * sc[t + 512] + bi[t + 512]);
}

// ---------------- fp16 MMA GEMM: 128x128 tile, 8 warps 64x32, BK=32, 4-stage -
template <int DOGELU, int OUTT>
__global__ void __launch_bounds__(256, 2)
k_mma_t(const unsigned* __restrict__ At, const unsigned* __restrict__ Bt,
        float* __restrict__ C, unsigned* __restrict__ Ct,
        int N, int K, int KtOut,
        const float* __restrict__ bias, const float* __restrict__ resid) {
    extern __shared__ uint4 sm4[];   // [4][1024] uint4 = 64KB
    const int bm = blockIdx.x * 128, bn = blockIdx.y * 128;
    const int tid = threadIdx.x;
    const int lane = tid & 31, warp = tid >> 5;
    const int wm = (warp & 1) * 64, wn = (warp >> 1) * 32;
    const int gid = lane >> 2, cid = lane & 3;
    const int K16 = K >> 4;

    const uint4* gA = (const uint4*)(At + ((size_t)blockIdx.x * K16) * 1024);
    const uint4* gB = (const uint4*)(Bt + ((size_t)blockIdx.y * K16) * 1024);
    const uint32_t s0 = smem_u32(&sm4[0]);
    const uint32_t sAld = s0 + tid * 16;
    const uint32_t sBld = s0 + 8192 + tid * 16;

    float acc[4][4][4];
#pragma unroll
    for (int i = 0; i < 4; i++)
#pragma unroll
        for (int j = 0; j < 4; j++)
#pragma unroll
            for (int r = 0; r < 4; r++) acc[i][j][r] = 0.f;

    const int nk = K >> 5;   // BK=32 = 2 k16-slabs per kt
#pragma unroll
    for (int st = 0; st < 3; st++) {
        const uint4* gAn = gA + st * 512;
        const uint4* gBn = gB + st * 512;
        uint32_t off = st * 16384;
#pragma unroll
        for (int i = 0; i < 2; i++) {
            cpa16(sAld + off + i * 4096, gAn + i * 256 + tid);
            cpa16(sBld + off + i * 4096, gBn + i * 256 + tid);
        }
        CP_COMMIT();
    }

    int s = 0;
    for (int kt = 0; kt < nk; kt++) {
        if (kt + 2 < nk)      { CP_WAIT2(); }
        else if (kt + 1 < nk) { CP_WAIT1(); }
        else                  { CP_WAIT0(); }
        __syncthreads();
        if (kt + 3 < nk) {
            const uint4* gAn = gA + (kt + 3) * 512;
            const uint4* gBn = gB + (kt + 3) * 512;
            int sn = s + 3; if (sn >= 4) sn -= 4;
            uint32_t off = sn * 16384;
#pragma unroll
            for (int i = 0; i < 2; i++) {
                cpa16(sAld + off + i * 4096, gAn + i * 256 + tid);
                cpa16(sBld + off + i * 4096, gBn + i * 256 + tid);
            }
            CP_COMMIT();
        }
        const uint4* sa = &sm4[s * 1024];
        const uint4* sb = sa + 512;
#pragma unroll
        for (int ks = 0; ks < 2; ks++) {
            uint4 af[4];
#pragma unroll
            for (int mi = 0; mi < 4; mi++)
                af[mi] = sa[ks * 256 + ((wm >> 4) + mi) * 32 + lane];
            uint4 bq[2];
#pragma unroll
            for (int nt = 0; nt < 2; nt++)
                bq[nt] = sb[ks * 256 + ((wn >> 4) + nt) * 32 + lane];
            unsigned bf[4][2] = {
                {bq[0].x, bq[0].y}, {bq[0].z, bq[0].w},
                {bq[1].x, bq[1].y}, {bq[1].z, bq[1].w}};
#pragma unroll
            for (int mi = 0; mi < 4; mi++)
#pragma unroll
                for (int ni = 0; ni < 4; ni++)
                    mma16(acc[mi][ni], (const unsigned*)&af[mi], bf[ni]);
        }
        if (++s == 4) s = 0;
    }

#pragma unroll
    for (int mi = 0; mi < 4; mi++) {
        int r0 = bm + wm + mi * 16 + gid;
#pragma unroll
        for (int ni = 0; ni < 4; ni++) {
            int c0 = bn + wn + ni * 8 + 2 * cid;
            float v00 = acc[mi][ni][0], v01 = acc[mi][ni][1];
            float v10 = acc[mi][ni][2], v11 = acc[mi][ni][3];
            if (bias) {
                float b0v = bias[c0], b1v = bias[c0 + 1];
                v00 += b0v; v01 += b1v; v10 += b0v; v11 += b1v;
            }
            if (resid) {
                const float* rr0 = resid + (size_t)r0 * N + c0;
                const float* rr1 = resid + (size_t)(r0 + 8) * N + c0;
                v00 += rr0[0]; v01 += rr0[1]; v10 += rr1[0]; v11 += rr1[1];
            }
            if (DOGELU) {
                v00 = 0.5f * v00 * (1.0f + erff(v00 * 0.70710678118654752f));
                v01 = 0.5f * v01 * (1.0f + erff(v01 * 0.70710678118654752f));
                v10 = 0.5f * v10 * (1.0f + erff(v10 * 0.70710678118654752f));
                v11 = 0.5f * v11 * (1.0f + erff(v11 * 0.70710678118654752f));
            }
            if (OUTT == 0) {
                *(float2*)&C[(size_t)r0 * N + c0]       = make_float2(v00, v01);
                *(float2*)&C[(size_t)(r0 + 8) * N + c0] = make_float2(v10, v11);
            } else {
                Ct[a16u(KtOut, r0, c0)]     = f2h2(v00, v01);
                Ct[a16u(KtOut, r0 + 8, c0)] = f2h2(v10, v11);
            }
        }
    }
}

// ---------------- half-height fp16 GEMM for N=768: 64x128 tile --------------
__global__ void __launch_bounds__(256, 3)
k_mma_h(const unsigned* __restrict__ At, const unsigned* __restrict__ Bt,
        float* __restrict__ C, int N, int K,
        const float* __restrict__ bias, const float* __restrict__ resid) {
    extern __shared__ uint4 sm4[];   // [3][768] uint4 = 36KB
    const int bm = blockIdx.x * 64, bn = blockIdx.y * 128;
    const int tid = threadIdx.x;
    const int lane = tid & 31, warp = tid >> 5;
    const int wm = (warp & 1) * 32, wn = (warp >> 1) * 32;
    const int gid = lane >> 2, cid = lane & 3;
    const int K16 = K >> 4;
    const int half = (blockIdx.x & 1) * 128;

    const uint4* gA = (const uint4*)(At + ((size_t)(blockIdx.x >> 1) * K16) * 1024);
    const uint4* gB = (const uint4*)(Bt + ((size_t)blockIdx.y * K16) * 1024);
    const uint32_t s0 = smem_u32(&sm4[0]);

    float acc[2][4][4];
#pragma unroll
    for (int i = 0; i < 2; i++)
#pragma unroll
        for (int j = 0; j < 4; j++)
#pragma unroll
            for (int r = 0; r < 4; r++) acc[i][j][r] = 0.f;

    const int nk = K >> 5;
#pragma unroll
    for (int st = 0; st < 2; st++) {
        uint32_t off = st * 12288;
        cpa16(s0 + off + tid * 16, gA + (st * 2 + (tid >> 7)) * 256 + half + (tid & 127));
#pragma unroll
        for (int i = 0; i < 2; i++)
            cpa16(s0 + off + 4096 + (i * 256 + tid) * 16, gB + st * 512 + i * 256 + tid);
        CP_COMMIT();
    }

    int s = 0;
    for (int kt = 0; kt < nk; kt++) {
        if (kt < nk - 1) { CP_WAIT1(); } else { CP_WAIT0(); }
        __syncthreads();
        if (kt + 2 < nk) {
            int sn = s + 2; if (sn >= 3) sn -= 3;
            uint32_t off = sn * 12288;
            cpa16(s0 + off + tid * 16,
                  gA + ((kt + 2) * 2 + (tid >> 7)) * 256 + half + (tid & 127));
#pragma unroll
            for (int i = 0; i < 2; i++)
                cpa16(s0 + off + 4096 + (i * 256 + tid) * 16,
                      gB + (kt + 2) * 512 + i * 256 + tid);
            CP_COMMIT();
        }
        const uint4* sa = &sm4[s * 768];
        const uint4* sb = sa + 256;
#pragma unroll
        for (int ks = 0; ks < 2; ks++) {
            uint4 af[2];
#pragma unroll
            for (int mi = 0; mi < 2; mi++)
                af[mi] = sa[ks * 128 + ((wm >> 4) + mi) * 32 + lane];
            uint4 bq[2];
#pragma unroll
            for (int nt = 0; nt < 2; nt++)
                bq[nt] = sb[ks * 256 + ((wn >> 4) + nt) * 32 + lane];
            unsigned bf[4][2] = {
                {bq[0].x, bq[0].y}, {bq[0].z, bq[0].w},
                {bq[1].x, bq[1].y}, {bq[1].z, bq[1].w}};
#pragma unroll
            for (int mi = 0; mi < 2; mi++)
#pragma unroll
                for (int ni = 0; ni < 4; ni++)
                    mma16(acc[mi][ni], (const unsigned*)&af[mi], bf[ni]);
        }
        if (++s == 3) s = 0;
    }

#pragma unroll
    for (int mi = 0; mi < 2; mi++) {
        int r0 = bm + wm + mi * 16 + gid;
#pragma unroll
        for (int ni = 0; ni < 4; ni++) {
            int c0 = bn + wn + ni * 8 + 2 * cid;
            float v00 = acc[mi][ni][0], v01 = acc[mi][ni][1];
            float v10 = acc[mi][ni][2], v11 = acc[mi][ni][3];
            if (bias) {
                float b0v = bias[c0], b1v = bias[c0 + 1];
                v00 += b0v; v01 += b1v; v10 += b0v; v11 += b1v;
            }
            if (resid) {
                const float* rr0 = resid + (size_t)r0 * N + c0;
                const float* rr1 = resid + (size_t)(r0 + 8) * N + c0;
                v00 += rr0[0]; v01 += rr0[1]; v10 += rr1[0]; v11 += rr1[1];
            }
            *(float2*)&C[(size_t)r0 * N + c0]       = make_float2(v00, v01);
            *(float2*)&C[(size_t)(r0 + 8) * N + c0] = make_float2(v10, v11);
        }
    }
}

// ---------------- fused flash attention on fp16 tensor cores ----------------
// 128 threads = 4 warps; warp w owns queries [i0+16w, i0+16w+16).
// smem (uint): uQ[2048] | uK[2048] | uV[2048] | uP[2048] = 32KB
__global__ void __launch_bounds__(128)
k_attn_mma(const float* __restrict__ qkv) {
    extern __shared__ unsigned us[];
    unsigned* uQ = us;
    unsigned* uK = us + 2048;
    unsigned* uV = us + 4096;
    unsigned* uP = us + 6144;
    __shared__ int sSeg[64], sGk[64], sVa[64];

    const int bh = blockIdx.y;
    const int b = bh / H_, h = bh % H_;
    const int i0 = (gridDim.x - 1 - blockIdx.x) * 64;
    const int tid = threadIdx.x;
    const int lane = tid & 31, w = tid >> 5;
    const int gid = lane >> 2, cid = lane & 3;

    // stage Q as per-warp fp16 A-fragments (once)
    const float* qb = qkv + (size_t)(b * L_ + i0) * (3 * D_) + h * HD_;
    for (int idx = tid; idx < 2048; idx += 128) {
        int r = idx >> 5, kp = idx & 31;
        const float* p = qb + (size_t)r * (3 * D_) + 2 * kp;
        uQ[q16u(r >> 4, r & 15, 2 * kp)] = f2h2(p[0], p[1]);
    }
    const int gi0 = i0 + w * 16 + gid;
    const int gi1 = gi0 + 8;
    const int si0 = g_seg[b * L_ + gi0];
    const int si1 = g_seg[b * L_ + gi1];

    float m0 = -1e30f, m1 = -1e30f, l0 = 0.f, l1 = 0.f;
    float o[8][4];
#pragma unroll
    for (int i = 0; i < 8; i++)
#pragma unroll
        for (int r = 0; r < 4; r++) o[i][r] = 0.f;

    const uint4* uQ4 = (const uint4*)uQ;
    const uint4* uK4 = (const uint4*)uK;
    const uint4* uV4 = (const uint4*)uV;
    const uint4* uP4 = (const uint4*)uP;

    for (int j0 = 0; j0 <= i0; j0 += 64) {
        __syncthreads();
        const float* kb = qkv + (size_t)(b * L_ + j0) * (3 * D_) + D_ + h * HD_;
        const float* vb = qkv + (size_t)(b * L_ + j0) * (3 * D_) + 2 * D_ + h * HD_;
        for (int idx = tid; idx < 2048; idx += 128) {
            int r = idx >> 5, cp = idx & 31;
            const float* pk = kb + (size_t)r * (3 * D_) + 2 * cp;
            uK[kb16u(r, 2 * cp)] = f2h2(pk[0], pk[1]);
            // V transposed: n=hd(r index role swapped), k=key pair
            const float* pv0 = vb + (size_t)(2 * cp) * (3 * D_) + r;
            const float* pv1 = pv0 + 3 * D_;
            uV[kb16u(r, 2 * cp)] = f2h2(pv0[0], pv1[0]);  // n=hd r, keys 2cp,2cp+1
        }
        if (tid < 64) {
            int gj = b * L_ + j0 + tid;
            sSeg[tid] = g_seg[gj];
            sGk[tid]  = g_gkey[gj];
            sVa[tid]  = g_valid[gj];
        }
        __syncthreads();

        // S = Q K^T (fp16 tensor pipe)
        float sreg[8][4];
#pragma unroll
        for (int i = 0; i < 8; i++)
#pragma unroll
            for (int r = 0; r < 4; r++) sreg[i][r] = 0.f;
#pragma unroll
        for (int ks = 0; ks < 4; ks++) {
            uint4 aq = uQ4[(w * 4 + ks) * 32 + lane];
            uint4 bq[4];
#pragma unroll
            for (int nt = 0; nt < 4; nt++)
                bq[nt] = uK4[ks * 128 + nt * 32 + lane];
            unsigned bf[8][2] = {
                {bq[0].x, bq[0].y}, {bq[0].z, bq[0].w},
                {bq[1].x, bq[1].y}, {bq[1].z, bq[1].w},
                {bq[2].x, bq[2].y}, {bq[2].z, bq[2].w},
                {bq[3].x, bq[3].y}, {bq[3].z, bq[3].w}};
#pragma unroll
            for (int ni = 0; ni < 8; ni++)
                mma16(sreg[ni], (const unsigned*)&aq, bf[ni]);
        }

        // mask + scale
#pragma unroll
        for (int nt = 0; nt < 8; nt++) {
#pragma unroll
            for (int bb = 0; bb < 2; bb++) {
                int cj = nt * 8 + 2 * cid + bb;
                int gj = j0 + cj;
                bool base = sVa[cj] != 0;
                bool a0 = base && (gj <= gi0) &&
                          (sSeg[cj] == si0 || sGk[cj] || (gi0 - gj) <= WIN_);
                bool a1 = base && (gj <= gi1) &&
                          (sSeg[cj] == si1 || sGk[cj] || (gi1 - gj) <= WIN_);
                sreg[nt][bb]     = a0 ? sreg[nt][bb] * 0.125f     : -1e30f;
                sreg[nt][2 + bb] = a1 ? sreg[nt][2 + bb] * 0.125f : -1e30f;
            }
        }

        // online softmax
        float vm0 = -1e30f, vm1 = -1e30f;
#pragma unroll
        for (int nt = 0; nt < 8; nt++) {
            vm0 = fmaxf(vm0, fmaxf(sreg[nt][0], sreg[nt][1]));
            vm1 = fmaxf(vm1, fmaxf(sreg[nt][2], sreg[nt][3]));
        }
#pragma unroll
        for (int off = 1; off <= 2; off <<= 1) {
            vm0 = fmaxf(vm0, __shfl_xor_sync(0xffffffffu, vm0, off));
            vm1 = fmaxf(vm1, __shfl_xor_sync(0xffffffffu, vm1, off));
        }
        float mn0 = fmaxf(m0, vm0), mn1 = fmaxf(m1, vm1);
        float al0 = __expf(m0 - mn0), al1 = __expf(m1 - mn1);
        m0 = mn0; m1 = mn1;
        float rs0 = 0.f, rs1 = 0.f;
#pragma unroll
        for (int nt = 0; nt < 8; nt++) {
            float p00 = (sreg[nt][0] > -1e29f) ? __expf(sreg[nt][0] - mn0) : 0.f;
            float p01 = (sreg[nt][1] > -1e29f) ? __expf(sreg[nt][1] - mn0) : 0.f;
            float p10 = (sreg[nt][2] > -1e29f) ? __expf(sreg[nt][2] - mn1) : 0.f;
            float p11 = (sreg[nt][3] > -1e29f) ? __expf(sreg[nt][3] - mn1) : 0.f;
            rs0 += p00 + p01;
            rs1 += p10 + p11;
            int k0 = nt * 8 + 2 * cid;   // even; pair (k0, k0+1)
            uP[q16u(w, gid, k0)]     = f2h2(p00, p01);
            uP[q16u(w, gid + 8, k0)] = f2h2(p10, p11);
        }
#pragma unroll
        for (int off = 1; off <= 2; off <<= 1) {
            rs0 += __shfl_xor_sync(0xffffffffu, rs0, off);
            rs1 += __shfl_xor_sync(0xffffffffu, rs1, off);
        }
        l0 = l0 * al0 + rs0;
        l1 = l1 * al1 + rs1;
#pragma unroll
        for (int nt = 0; nt < 8; nt++) {
            o[nt][0] *= al0; o[nt][1] *= al0;
            o[nt][2] *= al1; o[nt][3] *= al1;
        }
        __syncwarp();

        // O += P @ V (fp16 tensor pipe)
#pragma unroll
        for (int ks = 0; ks < 4; ks++) {
            uint4 ap = uP4[(w * 4 + ks) * 32 + lane];
            uint4 bq[4];
#pragma unroll
            for (int nt = 0; nt < 4; nt++)
                bq[nt] = uV4[ks * 128 + nt * 32 + lane];
            unsigned bf[8][2] = {
                {bq[0].x, bq[0].y}, {bq[0].z, bq[0].w},
                {bq[1].x, bq[1].y}, {bq[1].z, bq[1].w},
                {bq[2].x, bq[2].y}, {bq[2].z, bq[2].w},
                {bq[3].x, bq[3].y}, {bq[3].z, bq[3].w}};
#pragma unroll
            for (int ni = 0; ni < 8; ni++)
                mma16(o[ni], (const unsigned*)&ap, bf[ni]);
        }
        __syncwarp();
    }

    float inv0 = 1.0f / l0, inv1 = 1.0f / l1;
    int mr0 = b * L_ + gi0, mr1 = b * L_ + gi1;
#pragma unroll
    for (int nt = 0; nt < 8; nt++) {
        int c0 = h * HD_ + nt * 8 + 2 * cid;
        g_yt[a16u(D_, mr0, c0)] = f2h2(o[nt][0] * inv0, o[nt][1] * inv0);
        g_yt[a16u(D_, mr1, c0)] = f2h2(o[nt][2] * inv1, o[nt][3] * inv1);
    }
}

// ---------------- host side --------------------------------------------------
#define GEMM_SMEM_  65536
#define GEMMH_SMEM_ 36864
#define ATTN_SMEM_  32768

static void gemm_t(const unsigned* At, const unsigned* Bt, float* C, unsigned* Ct,
                   int N, int K, int ktout, const float* bias, const float* resid,
                   bool gelu_tiled) {
    if (N == D_) {
        dim3 grid(M_ / 64, N / 128);
        k_mma_h<<<grid, 256, GEMMH_SMEM_>>>(At, Bt, C, N, K, bias, resid);
        return;
    }
    dim3 grid(M_ / 128, N / 128);
    if (gelu_tiled)
        k_mma_t<1, 1><<<grid, 256, GEMM_SMEM_>>>(At, Bt, C, Ct, N, K, ktout, bias, resid);
    else
        k_mma_t<0, 0><<<grid, 256, GEMM_SMEM_>>>(At, Bt, C, Ct, N, K, ktout, bias, resid);
}

extern "C" void kernel_launch(void* const* d_in, const int* in_sizes, int n_in,
                              void* d_out, int out_size) {
    const int*   tokens    = (const int*)d_in[0];
    const int*   types     = (const int*)d_in[1];
    const int*   attn_mask = (const int*)d_in[2];
    const float* tok_emb   = (const float*)d_in[3];
    const float* type_emb  = (const float*)d_in[4];
    const float* pos_emb   = (const float*)d_in[5];
    const float* qkv_w     = (const float*)d_in[6];
    const float* out_w     = (const float*)d_in[7];
    const float* ln1_s     = (const float*)d_in[8];
    const float* ln1_b     = (const float*)d_in[9];
    const float* ln2_s     = (const float*)d_in[10];
    const float* ln2_b     = (const float*)d_in[11];
    const float* ff_w1     = (const float*)d_in[12];
    const float* ff_b1     = (const float*)d_in[13];
    const float* ff_w2     = (const float*)d_in[14];
    const float* ff_b2     = (const float*)d_in[15];
    const float* lnf_s     = (const float*)d_in[16];
    const float* lnf_b     = (const float*)d_in[17];
    const float* head_w    = (const float*)d_in[18];
    float* out = (float*)d_out;

    cudaFuncSetAttribute(k_mma_t<0, 0>, cudaFuncAttributeMaxDynamicSharedMemorySize, GEMM_SMEM_);
    cudaFuncSetAttribute(k_mma_t<1, 1>, cudaFuncAttributeMaxDynamicSharedMemorySize, GEMM_SMEM_);
    cudaFuncSetAttribute(k_mma_h, cudaFuncAttributeMaxDynamicSharedMemorySize, GEMMH_SMEM_);
    cudaFuncSetAttribute(k_attn_mma, cudaFuncAttributeMaxDynamicSharedMemorySize, ATTN_SMEM_);

    float *x, *qkv;
    unsigned *ht, *yt, *ft, *wqt, *wot, *w1t, *w2t, *wht;
    cudaGetSymbolAddress((void**)&x, g_x);
    cudaGetSymbolAddress((void**)&qkv, g_qkv);
    cudaGetSymbolAddress((void**)&ht, g_ht);
    cudaGetSymbolAddress((void**)&yt, g_yt);
    cudaGetSymbolAddress((void**)&ft, g_ft);
    cudaGetSymbolAddress((void**)&wqt, g_wqt);
    cudaGetSymbolAddress((void**)&wot, g_wot);
    cudaGetSymbolAddress((void**)&w1t, g_w1t);
    cudaGetSymbolAddress((void**)&w2t, g_w2t);
    cudaGetSymbolAddress((void**)&wht, g_wht);

    k_cvt_all<<<(int)((CVT_PAIRS + 255) / 256), 256>>>(qkv_w, out_w, ff_w1, ff_w2, head_w);
    k_embed<<<(M_ * D_ + 255) / 256, 256>>>(tokens, types, tok_emb, type_emb, pos_emb);
    k_ln_t<<<M_, 256>>>(x, ln1_s, ln1_b, ht);
    gemm_t(ht, wqt, qkv, nullptr, 3 * D_, D_, 0, nullptr, nullptr, false);
    k_maskprep<<<1, 32>>>(tokens, attn_mask);

    for (int l = 0; l < NL_; l++) {
        size_t wq_off = (size_t)l * 3 * D_ * D_ / 2;
        size_t wo_off = (size_t)l * D_ * D_ / 2;
        size_t w1_off = (size_t)l * FF_ * D_ / 2;
        size_t w2_off = (size_t)l * D_ * FF_ / 2;

        if (l > 0) {
            k_ln_t<<<M_, 256>>>(x, ln1_s + l * D_, ln1_b + l * D_, ht);
            gemm_t(ht, wqt + wq_off, qkv, nullptr, 3 * D_, D_, 0, nullptr, nullptr, false);
        }
        k_attn_mma<<<dim3(L_ / 64, B_ * H_), 128, ATTN_SMEM_>>>(qkv);
        gemm_t(yt, wot + wo_off, x, nullptr, D_, D_, 0, nullptr, x, false);
        k_ln_t<<<M_, 256>>>(x, ln2_s + l * D_, ln2_b + l * D_, ht);
        gemm_t(ht, w1t + w1_off, nullptr, ft, FF_, D_, FF_, ff_b1 + l * FF_, nullptr, true);
        gemm_t(ft, w2t + w2_off, x, nullptr, D_, FF_, 0, ff_b2 + l * D_, x, false);
    }
    k_ln_t<<<M_, 256>>>(x, lnf_s, lnf_b, ht);
    gemm_t(ht, wht, out, nullptr, V_, D_, 0, nullptr, nullptr, false);
}

// round 17
// speedup vs baseline: 1.0223x; 1.0223x over previous
#include <cuda_runtime.h>
#include <cuda_fp16.h>
#include <math.h>
#include <stdint.h>

#define B_ 2
#define L_ 1024
#define D_ 768
#define H_ 12
#define HD_ 64
#define FF_ 3072
#define V_ 32000
#define NL_ 2
#define TOK_BOS 1
#define TOK_SEP 2
#define WIN_ 512
#define EPS_ 1e-5f
#define M_ (B_ * L_) /* 2048 rows */

// ---------------- scratch (static device globals; no allocation) ------------
__device__ float g_x[M_ * D_];
__device__ float g_qkv[M_ * 3 * D_];
__device__ int   g_seg[B_ * L_];
__device__ int   g_gkey[B_ * L_];
__device__ int   g_valid[B_ * L_];

// fragment-major fp16x2 operand buffers (uint32 = 2 packed halves)
__device__ unsigned g_ht[M_ * D_ / 2];
__device__ unsigned g_yt[M_ * D_ / 2];
__device__ unsigned g_ft[M_ * FF_ / 2];
__device__ unsigned g_wqt[NL_ * 3 * D_ * D_ / 2];
__device__ unsigned g_wot[NL_ * D_ * D_ / 2];
__device__ unsigned g_w1t[NL_ * FF_ * D_ / 2];
__device__ unsigned g_w2t[NL_ * D_ * FF_ / 2];
__device__ unsigned g_wht[V_ * D_ / 2];

// ---------------- helpers ----------------------------------------------------
__device__ __forceinline__ unsigned f2h2(float a, float b) {
    __half2 h = __floats2half2_rn(a, b);
    return *(unsigned*)&h;
}
__device__ __forceinline__ uint32_t smem_u32(const void* p) {
    uint32_t a;
    asm("{ .reg .u64 t; cvta.to.shared.u64 t, %1; cvt.u32.u64 %0, t; }" : "=r"(a) : "l"(p));
    return a;
}
__device__ __forceinline__ void cpa16(uint32_t s, const void* g) {
    asm volatile("cp.async.cg.shared.global [%0], [%1], 16;" :: "r"(s), "l"(g));
}
#define CP_COMMIT() asm volatile("cp.async.commit_group;" ::: "memory")
#define CP_WAIT1()  asm volatile("cp.async.wait_group 1;" ::: "memory")
#define CP_WAIT0()  asm volatile("cp.async.wait_group 0;" ::: "memory")

// fp16 m16n8k16
__device__ __forceinline__ void mma16(float* c, const unsigned* a, const unsigned* b) {
    asm volatile(
        "mma.sync.aligned.m16n8k16.row.col.f32.f16.f16.f32 "
        "{%0,%1,%2,%3}, {%4,%5,%6,%7}, {%8,%9}, {%0,%1,%2,%3};\n"
        : "+f"(c[0]), "+f"(c[1]), "+f"(c[2]), "+f"(c[3])
        : "r"(a[0]), "r"(a[1]), "r"(a[2]), "r"(a[3]), "r"(b[0]), "r"(b[1]));
}

// fp16 fragment-major uint indices: 1024 uints per (128row x 16k) slab.
__device__ __forceinline__ size_t a16u(int Kd, int m, int c) {
    return ((size_t)(m >> 7) * (Kd >> 4) + (c >> 4)) * 1024
         + (size_t)(((m & 127) >> 4) * 128)
         + (((m & 7) * 4 + ((c >> 1) & 3)) << 2)
         + ((m & 15) >> 3) + 2 * ((c & 15) >> 3);
}
__device__ __forceinline__ size_t b16u(int Kd, int n, int k) {
    return ((size_t)(n >> 7) * (Kd >> 4) + (k >> 4)) * 1024
         + (size_t)(((n & 127) >> 4) * 128)
         + (((n & 7) * 4 + ((k >> 1) & 3)) << 2)
         + ((k & 15) >> 3) + 2 * ((n & 15) >> 3);
}
// fp16 64x64 attention-tile fragment indices (uint index)
__device__ __forceinline__ int q16u(int w, int m, int k) {
    return (w * 4 + (k >> 4)) * 128
         + (((m & 7) * 4 + ((k >> 1) & 3)) << 2)
         + ((m & 15) >> 3) + 2 * ((k & 15) >> 3);
}
__device__ __forceinline__ int kb16u(int n, int k) {
    return (k >> 4) * 512 + (n >> 4) * 128
         + (((n & 7) * 4 + ((k >> 1) & 3)) << 2)
         + ((k & 15) >> 3) + 2 * ((n & 15) >> 3);
}

// ---------------- embedding -------------------------------------------------
__global__ void k_embed(const int* __restrict__ tokens, const int* __restrict__ types,
                        const float* __restrict__ tok_emb, const float* __restrict__ type_emb,
                        const float* __restrict__ pos_emb) {
    int idx = blockIdx.x * blockDim.x + threadIdx.x;
    if (idx >= M_ * D_) return;
    int d = idx % D_;
    int bl = idx / D_;
    int l = bl % L_;
    g_x[idx] = tok_emb[(size_t)tokens[bl] * D_ + d]
             + type_emb[(size_t)types[bl] * D_ + d]
             + pos_emb[(size_t)l * D_ + d];
}

// ---------------- mask metadata ----------------------------------------------
__global__ void k_maskprep(const int* __restrict__ tokens, const int* __restrict__ attn_mask) {
    int b = threadIdx.x;
    if (b >= B_) return;
    int seg = 0;
    for (int l = 0; l < L_; l++) {
        int i = b * L_ + l;
        int va = attn_mask[i] != 0;
        int tok = tokens[i];
        int is_sep = (tok == TOK_SEP) && va;
        seg += is_sep;
        g_seg[i] = seg;
        g_gkey[i] = (((tok == TOK_BOS) && va) || is_sep) ? 1 : 0;
        g_valid[i] = va;
    }
}

// ---------------- all weight conversions (pair-packed uint stores) ----------
#define SZ_WQ (NL_ * 3 * D_ * D_)
#define SZ_WO (NL_ * D_ * D_)
#define SZ_W1 (NL_ * FF_ * D_)
#define SZ_W2 (NL_ * D_ * FF_)
#define SZ_WH (V_ * D_)
#define CVT_PAIRS ((SZ_WQ + SZ_WO + SZ_W1 + SZ_W2 + SZ_WH) / 2)

__global__ void k_cvt_all(const float* __restrict__ qkv_w, const float* __restrict__ out_w,
                          const float* __restrict__ ff_w1, const float* __restrict__ ff_w2,
                          const float* __restrict__ head_w) {
    long p = (long)blockIdx.x * 256 + threadIdx.x;
    if (p < SZ_WQ / 2) {
        int n = (int)(p / (D_ / 2)), k = 2 * (int)(p % (D_ / 2));
        const float* w = qkv_w + (size_t)n * D_ + k;
        g_wqt[b16u(D_, n, k)] = f2h2(w[0], w[1]);
        return;
    }
    p -= SZ_WQ / 2;
    if (p < SZ_WO / 2) {
        int n = (int)(p / (D_ / 2)), k = 2 * (int)(p % (D_ / 2));
        const float* w = out_w + (size_t)n * D_ + k;
        g_wot[b16u(D_, n, k)] = f2h2(w[0], w[1]);
        return;
    }
    p -= SZ_WO / 2;
    if (p < SZ_W1 / 2) {
        int n = (int)(p / (D_ / 2)), k = 2 * (int)(p % (D_ / 2));
        const float* w = ff_w1 + (size_t)n * D_ + k;
        g_w1t[b16u(D_, n, k)] = f2h2(w[0], w[1]);
        return;
    }
    p -= SZ_W1 / 2;
    if (p < SZ_W2 / 2) {
        int n = (int)(p / (FF_ / 2)), k = 2 * (int)(p % (FF_ / 2));
        const float* w = ff_w2 + (size_t)n * FF_ + k;
        g_w2t[b16u(FF_, n, k)] = f2h2(w[0], w[1]);
        return;
    }
    p -= SZ_W2 / 2;
    if (p < SZ_WH / 2) {
        int n = (int)(p / (D_ / 2)), k = 2 * (int)(p % (D_ / 2));
        const float* w = head_w + (size_t)n * D_ + k;
        g_wht[b16u(D_, n, k)] = f2h2(w[0], w[1]);
    }
}

// ---------------- layernorm -> A-tiled fp16 ----------------------------------
__global__ __launch_bounds__(256)
void k_ln_t(const float* __restrict__ x, const float* __restrict__ sc,
            const float* __restrict__ bi, unsigned* __restrict__ out) {
    int row = blockIdx.x;
    const float* xr = x + (size_t)row * D_;
    int t = threadIdx.x;
    float v0 = xr[t], v1 = xr[t + 256], v2 = xr[t + 512];
    float s = v0 + v1 + v2;
    float ss = v0 * v0 + v1 * v1 + v2 * v2;
    __shared__ float rs[8], rq[8];
#pragma unroll
    for (int o = 16; o > 0; o >>= 1) {
        s  += __shfl_xor_sync(0xffffffffu, s, o);
        ss += __shfl_xor_sync(0xffffffffu, ss, o);
    }
    if ((t & 31) == 0) { rs[t >> 5] = s; rq[t >> 5] = ss; }
    __syncthreads();
    if (t < 32) {
        float a = (t < 8) ? rs[t] : 0.f;
        float q = (t < 8) ? rq[t] : 0.f;
#pragma unroll
        for (int o = 4; o > 0; o >>= 1) {
            a += __shfl_xor_sync(0xffffffffu, a, o);
            q += __shfl_xor_sync(0xffffffffu, q, o);
        }
        if (t == 0) { rs[0] = a; rq[0] = q; }
    }
    __syncthreads();
    float mean = rs[0] * (1.0f / D_);
    float var  = rq[0] * (1.0f / D_) - mean * mean;
    float inv = rsqrtf(var + EPS_);
    __half* oh = (__half*)out;
    oh[2 * a16u(D_, row, t)       + (t & 1)] = __float2half_rn((v0 - mean) * inv * sc[t]       + bi[t]);
    oh[2 * a16u(D_, row, t + 256) + (t & 1)] = __float2half_rn((v1 - mean) * inv * sc[t + 256] + bi[t + 256]);
    oh[2 * a16u(D_, row, t + 512) + (t & 1)] = __float2half_rn((v2 - mean) * inv * sc[t + 512] + bi[t + 512]);
}

// ---------------- fp16 MMA GEMM: 128x128 tile, 8 warps 64x32, BK=64, 3-stage -
template <int DOGELU, int OUTT>
__global__ void __launch_bounds__(256, 2)
k_mma_t(const unsigned* __restrict__ At, const unsigned* __restrict__ Bt,
        float* __restrict__ C, unsigned* __restrict__ Ct,
        int N, int K, int KtOut,
        const float* __restrict__ bias, const float* __restrict__ resid) {
    extern __shared__ uint4 sm4[];   // [3][2048] uint4 = 96KB
    const int bm = blockIdx.x * 128, bn = blockIdx.y * 128;
    const int tid = threadIdx.x;
    const int lane = tid & 31, warp = tid >> 5;
    const int wm = (warp & 1) * 64, wn = (warp >> 1) * 32;
    const int gid = lane >> 2, cid = lane & 3;
    const int K16 = K >> 4;

    const uint4* gA = (const uint4*)(At + ((size_t)blockIdx.x * K16) * 1024);
    const uint4* gB = (const uint4*)(Bt + ((size_t)blockIdx.y * K16) * 1024);
    const uint32_t s0 = smem_u32(&sm4[0]);
    const uint32_t sAld = s0 + tid * 16;
    const uint32_t sBld = s0 + 16384 + tid * 16;

    float acc[4][4][4];
#pragma unroll
    for (int i = 0; i < 4; i++)
#pragma unroll
        for (int j = 0; j < 4; j++)
#pragma unroll
            for (int r = 0; r < 4; r++) acc[i][j][r] = 0.f;

    const int nk = K >> 6;   // BK=64 = 4 k16-slabs per kt
#pragma unroll
    for (int st = 0; st < 2; st++) {
        const uint4* gAn = gA + st * 1024;
        const uint4* gBn = gB + st * 1024;
        uint32_t off = st * 32768;
#pragma unroll
        for (int i = 0; i < 4; i++) {
            cpa16(sAld + off + i * 4096, gAn + i * 256 + tid);
            cpa16(sBld + off + i * 4096, gBn + i * 256 + tid);
        }
        CP_COMMIT();
    }

    int s = 0;
    for (int kt = 0; kt < nk; kt++) {
        if (kt < nk - 1) { CP_WAIT1(); } else { CP_WAIT0(); }
        __syncthreads();
        if (kt + 2 < nk) {
            const uint4* gAn = gA + (kt + 2) * 1024;
            const uint4* gBn = gB + (kt + 2) * 1024;
            int sn = s + 2; if (sn >= 3) sn -= 3;
            uint32_t off = sn * 32768;
#pragma unroll
            for (int i = 0; i < 4; i++) {
                cpa16(sAld + off + i * 4096, gAn + i * 256 + tid);
                cpa16(sBld + off + i * 4096, gBn + i * 256 + tid);
            }
            CP_COMMIT();
        }
        const uint4* sa = &sm4[s * 2048];
        const uint4* sb = sa + 1024;
#pragma unroll
        for (int ks = 0; ks < 4; ks++) {
            uint4 af[4];
#pragma unroll
            for (int mi = 0; mi < 4; mi++)
                af[mi] = sa[ks * 256 + ((wm >> 4) + mi) * 32 + lane];
            uint4 bq[2];
#pragma unroll
            for (int nt = 0; nt < 2; nt++)
                bq[nt] = sb[ks * 256 + ((wn >> 4) + nt) * 32 + lane];
            unsigned bf[4][2] = {
                {bq[0].x, bq[0].y}, {bq[0].z, bq[0].w},
                {bq[1].x, bq[1].y}, {bq[1].z, bq[1].w}};
#pragma unroll
            for (int mi = 0; mi < 4; mi++)
#pragma unroll
                for (int ni = 0; ni < 4; ni++)
                    mma16(acc[mi][ni], (const unsigned*)&af[mi], bf[ni]);
        }
        if (++s == 3) s = 0;
    }

#pragma unroll
    for (int mi = 0; mi < 4; mi++) {
        int r0 = bm + wm + mi * 16 + gid;
#pragma unroll
        for (int ni = 0; ni < 4; ni++) {
            int c0 = bn + wn + ni * 8 + 2 * cid;
            float v00 = acc[mi][ni][0], v01 = acc[mi][ni][1];
            float v10 = acc[mi][ni][2], v11 = acc[mi][ni][3];
            if (bias) {
                float b0v = bias[c0], b1v = bias[c0 + 1];
                v00 += b0v; v01 += b1v; v10 += b0v; v11 += b1v;
            }
            if (resid) {
                const float* rr0 = resid + (size_t)r0 * N + c0;
                const float* rr1 = resid + (size_t)(r0 + 8) * N + c0;
                v00 += rr0[0]; v01 += rr0[1]; v10 += rr1[0]; v11 += rr1[1];
            }
            if (DOGELU) {
                v00 = 0.5f * v00 * (1.0f + erff(v00 * 0.70710678118654752f));
                v01 = 0.5f * v01 * (1.0f + erff(v01 * 0.70710678118654752f));
                v10 = 0.5f * v10 * (1.0f + erff(v10 * 0.70710678118654752f));
                v11 = 0.5f * v11 * (1.0f + erff(v11 * 0.70710678118654752f));
            }
            if (OUTT == 0) {
                *(float2*)&C[(size_t)r0 * N + c0]       = make_float2(v00, v01);
                *(float2*)&C[(size_t)(r0 + 8) * N + c0] = make_float2(v10, v11);
            } else {
                Ct[a16u(KtOut, r0, c0)]     = f2h2(v00, v01);
                Ct[a16u(KtOut, r0 + 8, c0)] = f2h2(v10, v11);
            }
        }
    }
}

// ---------------- half-height fp16 GEMM for N=768: 64x128 tile, BK=64 -------
__global__ void __launch_bounds__(256, 3)
k_mma_h(const unsigned* __restrict__ At, const unsigned* __restrict__ Bt,
        float* __restrict__ C, int N, int K,
        const float* __restrict__ bias, const float* __restrict__ resid) {
    extern __shared__ uint4 sm4[];   // [3][1536] uint4 = 72KB
    const int bm = blockIdx.x * 64, bn = blockIdx.y * 128;
    const int tid = threadIdx.x;
    const int lane = tid & 31, warp = tid >> 5;
    const int wm = (warp & 1) * 32, wn = (warp >> 1) * 32;
    const int gid = lane >> 2, cid = lane & 3;
    const int K16 = K >> 4;
    const int half = (blockIdx.x & 1) * 128;

    const uint4* gA = (const uint4*)(At + ((size_t)(blockIdx.x >> 1) * K16) * 1024);
    const uint4* gB = (const uint4*)(Bt + ((size_t)blockIdx.y * K16) * 1024);
    const uint32_t s0 = smem_u32(&sm4[0]);

    float acc[2][4][4];
#pragma unroll
    for (int i = 0; i < 2; i++)
#pragma unroll
        for (int j = 0; j < 4; j++)
#pragma unroll
            for (int r = 0; r < 4; r++) acc[i][j][r] = 0.f;

    const int nk = K >> 6;   // BK=64
    // per kt: A 512 uint4 (64 rows x 4 slabs), B 1024 uint4 -> stage 1536 uint4
#pragma unroll
    for (int st = 0; st < 2; st++) {
        uint32_t off = st * 24576;
        {
            int idx = tid;
            cpa16(s0 + off + idx * 16, gA + (st * 4 + (idx >> 7)) * 256 + half + (idx & 127));
            idx = tid + 256;
            cpa16(s0 + off + idx * 16, gA + (st * 4 + (idx >> 7)) * 256 + half + (idx & 127));
        }
#pragma unroll
        for (int i = 0; i < 4; i++)
            cpa16(s0 + off + 8192 + (i * 256 + tid) * 16, gB + st * 1024 + i * 256 + tid);
        CP_COMMIT();
    }

    int s = 0;
    for (int kt = 0; kt < nk; kt++) {
        if (kt < nk - 1) { CP_WAIT1(); } else { CP_WAIT0(); }
        __syncthreads();
        if (kt + 2 < nk) {
            int sn = s + 2; if (sn >= 3) sn -= 3;
            uint32_t off = sn * 24576;
            {
                int idx = tid;
                cpa16(s0 + off + idx * 16,
                      gA + ((kt + 2) * 4 + (idx >> 7)) * 256 + half + (idx & 127));
                idx = tid + 256;
                cpa16(s0 + off + idx * 16,
                      gA + ((kt + 2) * 4 + (idx >> 7)) * 256 + half + (idx & 127));
            }
#pragma unroll
            for (int i = 0; i < 4; i++)
                cpa16(s0 + off + 8192 + (i * 256 + tid) * 16,
                      gB + (kt + 2) * 1024 + i * 256 + tid);
            CP_COMMIT();
        }
        const uint4* sa = &sm4[s * 1536];
        const uint4* sb = sa + 512;
#pragma unroll
        for (int ks = 0; ks < 4; ks++) {
            uint4 af[2];
#pragma unroll
            for (int mi = 0; mi < 2; mi++)
                af[mi] = sa[ks * 128 + ((wm >> 4) + mi) * 32 + lane];
            uint4 bq[2];
#pragma unroll
            for (int nt = 0; nt < 2; nt++)
                bq[nt] = sb[ks * 256 + ((wn >> 4) + nt) * 32 + lane];
            unsigned bf[4][2] = {
                {bq[0].x, bq[0].y}, {bq[0].z, bq[0].w},
                {bq[1].x, bq[1].y}, {bq[1].z, bq[1].w}};
#pragma unroll
            for (int mi = 0; mi < 2; mi++)
#pragma unroll
                for (int ni = 0; ni < 4; ni++)
                    mma16(acc[mi][ni], (const unsigned*)&af[mi], bf[ni]);
        }
        if (++s == 3) s = 0;
    }

#pragma unroll
    for (int mi = 0; mi < 2; mi++) {
        int r0 = bm + wm + mi * 16 + gid;
#pragma unroll
        for (int ni = 0; ni < 4; ni++) {
            int c0 = bn + wn + ni * 8 + 2 * cid;
            float v00 = acc[mi][ni][0], v01 = acc[mi][ni][1];
            float v10 = acc[mi][ni][2], v11 = acc[mi][ni][3];
            if (bias) {
                float b0v = bias[c0], b1v = bias[c0 + 1];
                v00 += b0v; v01 += b1v; v10 += b0v; v11 += b1v;
            }
            if (resid) {
                const float* rr0 = resid + (size_t)r0 * N + c0;
                const float* rr1 = resid + (size_t)(r0 + 8) * N + c0;
                v00 += rr0[0]; v01 += rr0[1]; v10 += rr1[0]; v11 += rr1[1];
            }
            *(float2*)&C[(size_t)r0 * N + c0]       = make_float2(v00, v01);
            *(float2*)&C[(size_t)(r0 + 8) * N + c0] = make_float2(v10, v11);
        }
    }
}

// ---------------- fused flash attention on fp16 tensor cores ----------------
__global__ void __launch_bounds__(128)
k_attn_mma(const float* __restrict__ qkv) {
    extern __shared__ unsigned us[];
    unsigned* uQ = us;
    unsigned* uK = us + 2048;
    unsigned* uV = us + 4096;
    unsigned* uP = us + 6144;
    __shared__ int sSeg[64], sGk[64], sVa[64];

    const int bh = blockIdx.y;
    const int b = bh / H_, h = bh % H_;
    const int i0 = (gridDim.x - 1 - blockIdx.x) * 64;
    const int tid = threadIdx.x;
    const int lane = tid & 31, w = tid >> 5;
    const int gid = lane >> 2, cid = lane & 3;

    const float* qb = qkv + (size_t)(b * L_ + i0) * (3 * D_) + h * HD_;
    for (int idx = tid; idx < 2048; idx += 128) {
        int r = idx >> 5, kp = idx & 31;
        const float* p = qb + (size_t)r * (3 * D_) + 2 * kp;
        uQ[q16u(r >> 4, r & 15, 2 * kp)] = f2h2(p[0], p[1]);
    }
    const int gi0 = i0 + w * 16 + gid;
    const int gi1 = gi0 + 8;
    const int si0 = g_seg[b * L_ + gi0];
    const int si1 = g_seg[b * L_ + gi1];

    float m0 = -1e30f, m1 = -1e30f, l0 = 0.f, l1 = 0.f;
    float o[8][4];
#pragma unroll
    for (int i = 0; i < 8; i++)
#pragma unroll
        for (int r = 0; r < 4; r++) o[i][r] = 0.f;

    const uint4* uQ4 = (const uint4*)uQ;
    const uint4* uK4 = (const uint4*)uK;
    const uint4* uV4 = (const uint4*)uV;
    const uint4* uP4 = (const uint4*)uP;

    for (int j0 = 0; j0 <= i0; j0 += 64) {
        __syncthreads();
        const float* kb = qkv + (size_t)(b * L_ + j0) * (3 * D_) + D_ + h * HD_;
        const float* vb = qkv + (size_t)(b * L_ + j0) * (3 * D_) + 2 * D_ + h * HD_;
        for (int idx = tid; idx < 2048; idx += 128) {
            int r = idx >> 5, cp = idx & 31;
            const float* pk = kb + (size_t)r * (3 * D_) + 2 * cp;
            uK[kb16u(r, 2 * cp)] = f2h2(pk[0], pk[1]);
            const float* pv0 = vb + (size_t)(2 * cp) * (3 * D_) + r;
            const float* pv1 = pv0 + 3 * D_;
            uV[kb16u(r, 2 * cp)] = f2h2(pv0[0], pv1[0]);
        }
        if (tid < 64) {
            int gj = b * L_ + j0 + tid;
            sSeg[tid] = g_seg[gj];
            sGk[tid]  = g_gkey[gj];
            sVa[tid]  = g_valid[gj];
        }
        __syncthreads();

        float sreg[8][4];
#pragma unroll
        for (int i = 0; i < 8; i++)
#pragma unroll
            for (int r = 0; r < 4; r++) sreg[i][r] = 0.f;
#pragma unroll
        for (int ks = 0; ks < 4; ks++) {
            uint4 aq = uQ4[(w * 4 + ks) * 32 + lane];
            uint4 bq[4];
#pragma unroll
            for (int nt = 0; nt < 4; nt++)
                bq[nt] = uK4[ks * 128 + nt * 32 + lane];
            unsigned bf[8][2] = {
                {bq[0].x, bq[0].y}, {bq[0].z, bq[0].w},
                {bq[1].x, bq[1].y}, {bq[1].z, bq[1].w},
                {bq[2].x, bq[2].y}, {bq[2].z, bq[2].w},
                {bq[3].x, bq[3].y}, {bq[3].z, bq[3].w}};
#pragma unroll
            for (int ni = 0; ni < 8; ni++)
                mma16(sreg[ni], (const unsigned*)&aq, bf[ni]);
        }

#pragma unroll
        for (int nt = 0; nt < 8; nt++) {
#pragma unroll
            for (int bb = 0; bb < 2; bb++) {
                int cj = nt * 8 + 2 * cid + bb;
                int gj = j0 + cj;
                bool base = sVa[cj] != 0;
                bool a0 = base && (gj <= gi0) &&
                          (sSeg[cj] == si0 || sGk[cj] || (gi0 - gj) <= WIN_);
                bool a1 = base && (gj <= gi1) &&
                          (sSeg[cj] == si1 || sGk[cj] || (gi1 - gj) <= WIN_);
                sreg[nt][bb]     = a0 ? sreg[nt][bb] * 0.125f     : -1e30f;
                sreg[nt][2 + bb] = a1 ? sreg[nt][2 + bb] * 0.125f : -1e30f;
            }
        }

        float vm0 = -1e30f, vm1 = -1e30f;
#pragma unroll
        for (int nt = 0; nt < 8; nt++) {
            vm0 = fmaxf(vm0, fmaxf(sreg[nt][0], sreg[nt][1]));
            vm1 = fmaxf(vm1, fmaxf(sreg[nt][2], sreg[nt][3]));
        }
#pragma unroll
        for (int off = 1; off <= 2; off <<= 1) {
            vm0 = fmaxf(vm0, __shfl_xor_sync(0xffffffffu, vm0, off));
            vm1 = fmaxf(vm1, __shfl_xor_sync(0xffffffffu, vm1, off));
        }
        float mn0 = fmaxf(m0, vm0), mn1 = fmaxf(m1, vm1);
        float al0 = __expf(m0 - mn0), al1 = __expf(m1 - mn1);
        m0 = mn0; m1 = mn1;
        float rs0 = 0.f, rs1 = 0.f;
#pragma unroll
        for (int nt = 0; nt < 8; nt++) {
            float p00 = (sreg[nt][0] > -1e29f) ? __expf(sreg[nt][0] - mn0) : 0.f;
            float p01 = (sreg[nt][1] > -1e29f) ? __expf(sreg[nt][1] - mn0) : 0.f;
            float p10 = (sreg[nt][2] > -1e29f) ? __expf(sreg[nt][2] - mn1) : 0.f;
            float p11 = (sreg[nt][3] > -1e29f) ? __expf(sreg[nt][3] - mn1) : 0.f;
            rs0 += p00 + p01;
            rs1 += p10 + p11;
            int k0 = nt * 8 + 2 * cid;
            uP[q16u(w, gid, k0)]     = f2h2(p00, p01);
            uP[q16u(w, gid + 8, k0)] = f2h2(p10, p11);
        }
#pragma unroll
        for (int off = 1; off <= 2; off <<= 1) {
            rs0 += __shfl_xor_sync(0xffffffffu, rs0, off);
            rs1 += __shfl_xor_sync(0xffffffffu, rs1, off);
        }
        l0 = l0 * al0 + rs0;
        l1 = l1 * al1 + rs1;
#pragma unroll
        for (int nt = 0; nt < 8; nt++) {
            o[nt][0] *= al0; o[nt][1] *= al0;
            o[nt][2] *= al1; o[nt][3] *= al1;
        }
        __syncwarp();

#pragma unroll
        for (int ks = 0; ks < 4; ks++) {
            uint4 ap = uP4[(w * 4 + ks) * 32 + lane];
            uint4 bq[4];
#pragma unroll
            for (int nt = 0; nt < 4; nt++)
                bq[nt] = uV4[ks * 128 + nt * 32 + lane];
            unsigned bf[8][2] = {
                {bq[0].x, bq[0].y}, {bq[0].z, bq[0].w},
                {bq[1].x, bq[1].y}, {bq[1].z, bq[1].w},
                {bq[2].x, bq[2].y}, {bq[2].z, bq[2].w},
                {bq[3].x, bq[3].y}, {bq[3].z, bq[3].w}};
#pragma unroll
            for (int ni = 0; ni < 8; ni++)
                mma16(o[ni], (const unsigned*)&ap, bf[ni]);
        }
        __syncwarp();
    }

    float inv0 = 1.0f / l0, inv1 = 1.0f / l1;
    int mr0 = b * L_ + gi0, mr1 = b * L_ + gi1;
#pragma unroll
    for (int nt = 0; nt < 8; nt++) {
        int c0 = h * HD_ + nt * 8 + 2 * cid;
        g_yt[a16u(D_, mr0, c0)] = f2h2(o[nt][0] * inv0, o[nt][1] * inv0);
        g_yt[a16u(D_, mr1, c0)] = f2h2(o[nt][2] * inv1, o[nt][3] * inv1);
    }
}

// ---------------- host side --------------------------------------------------
#define GEMM_SMEM_  98304
#define GEMMH_SMEM_ 73728
#define ATTN_SMEM_  32768

static void gemm_t(const unsigned* At, const unsigned* Bt, float* C, unsigned* Ct,
                   int N, int K, int ktout, const float* bias, const float* resid,
                   bool gelu_tiled) {
    if (N == D_) {
        dim3 grid(M_ / 64, N / 128);
        k_mma_h<<<grid, 256, GEMMH_SMEM_>>>(At, Bt, C, N, K, bias, resid);
        return;
    }
    dim3 grid(M_ / 128, N / 128);
    if (gelu_tiled)
        k_mma_t<1, 1><<<grid, 256, GEMM_SMEM_>>>(At, Bt, C, Ct, N, K, ktout, bias, resid);
    else
        k_mma_t<0, 0><<<grid, 256, GEMM_SMEM_>>>(At, Bt, C, Ct, N, K, ktout, bias, resid);
}

extern "C" void kernel_launch(void* const* d_in, const int* in_sizes, int n_in,
                              void* d_out, int out_size) {
    const int*   tokens    = (const int*)d_in[0];
    const int*   types     = (const int*)d_in[1];
    const int*   attn_mask = (const int*)d_in[2];
    const float* tok_emb   = (const float*)d_in[3];
    const float* type_emb  = (const float*)d_in[4];
    const float* pos_emb   = (const float*)d_in[5];
    const float* qkv_w     = (const float*)d_in[6];
    const float* out_w     = (const float*)d_in[7];
    const float* ln1_s     = (const float*)d_in[8];
    const float* ln1_b     = (const float*)d_in[9];
    const float* ln2_s     = (const float*)d_in[10];
    const float* ln2_b     = (const float*)d_in[11];
    const float* ff_w1     = (const float*)d_in[12];
    const float* ff_b1     = (const float*)d_in[13];
    const float* ff_w2     = (const float*)d_in[14];
    const float* ff_b2     = (const float*)d_in[15];
    const float* lnf_s     = (const float*)d_in[16];
    const float* lnf_b     = (const float*)d_in[17];
    const float* head_w    = (const float*)d_in[18];
    float* out = (float*)d_out;

    cudaFuncSetAttribute(k_mma_t<0, 0>, cudaFuncAttributeMaxDynamicSharedMemorySize, GEMM_SMEM_);
    cudaFuncSetAttribute(k_mma_t<1, 1>, cudaFuncAttributeMaxDynamicSharedMemorySize, GEMM_SMEM_);
    cudaFuncSetAttribute(k_mma_h, cudaFuncAttributeMaxDynamicSharedMemorySize, GEMMH_SMEM_);
    cudaFuncSetAttribute(k_attn_mma, cudaFuncAttributeMaxDynamicSharedMemorySize, ATTN_SMEM_);

    float *x, *qkv;
    unsigned *ht, *yt, *ft, *wqt, *wot, *w1t, *w2t, *wht;
    cudaGetSymbolAddress((void**)&x, g_x);
    cudaGetSymbolAddress((void**)&qkv, g_qkv);
    cudaGetSymbolAddress((void**)&ht, g_ht);
    cudaGetSymbolAddress((void**)&yt, g_yt);
    cudaGetSymbolAddress((void**)&ft, g_ft);
    cudaGetSymbolAddress((void**)&wqt, g_wqt);
    cudaGetSymbolAddress((void**)&wot, g_wot);
    cudaGetSymbolAddress((void**)&w1t, g_w1t);
    cudaGetSymbolAddress((void**)&w2t, g_w2t);
    cudaGetSymbolAddress((void**)&wht, g_wht);

    k_cvt_all<<<(int)((CVT_PAIRS + 255) / 256), 256>>>(qkv_w, out_w, ff_w1, ff_w2, head_w);
    k_embed<<<(M_ * D_ + 255) / 256, 256>>>(tokens, types, tok_emb, type_emb, pos_emb);
    k_ln_t<<<M_, 256>>>(x, ln1_s, ln1_b, ht);
    gemm_t(ht, wqt, qkv, nullptr, 3 * D_, D_, 0, nullptr, nullptr, false);
    k_maskprep<<<1, 32>>>(tokens, attn_mask);

    for (int l = 0; l < NL_; l++) {
        size_t wq_off = (size_t)l * 3 * D_ * D_ / 2;
        size_t wo_off = (size_t)l * D_ * D_ / 2;
        size_t w1_off = (size_t)l * FF_ * D_ / 2;
        size_t w2_off = (size_t)l * D_ * FF_ / 2;

        if (l > 0) {
            k_ln_t<<<M_, 256>>>(x, ln1_s + l * D_, ln1_b + l * D_, ht);
            gemm_t(ht, wqt + wq_off, qkv, nullptr, 3 * D_, D_, 0, nullptr, nullptr, false);
        }
        k_attn_mma<<<dim3(L_ / 64, B_ * H_), 128, ATTN_SMEM_>>>(qkv);
        gemm_t(yt, wot + wo_off, x, nullptr, D_, D_, 0, nullptr, x, false);
        k_ln_t<<<M_, 256>>>(x, ln2_s + l * D_, ln2_b + l * D_, ht);
        gemm_t(ht, w1t + w1_off, nullptr, ft, FF_, D_, FF_, ff_b1 + l * FF_, nullptr, true);
        gemm_t(ft, w2t + w2_off, x, nullptr, D_, FF_, 0, ff_b2 + l * D_, x, false);
    }
    k_ln_t<<<M_, 256>>>(x, lnf_s, lnf_b, ht);
    gemm_t(ht, wht, out, nullptr, V_, D_, 0, nullptr, nullptr, false);
}